// round 1
// baseline (speedup 1.0000x reference)
#include <cuda_runtime.h>
#include <math.h>

#define Bn   4
#define Nn   1024
#define Dn   1024
#define Hn   16
#define DHn  64
#define NOUT 3072   // q (1024) | k (1024) | v (1024)

// Scratch (allocation-free rule: __device__ globals)
__device__ float g_y[(size_t)Bn * Nn * NOUT];            // 50.3 MB: q|k|v
__device__ float g_s[(size_t)Bn * Hn * Nn * Nn];          // 256 MB: raw dots

// ---------------------------------------------------------------------------
// Kernel 1: Y = x @ [Wq ; Wkv]^T      (M=4096, N=3072, K=1024, fp32)
// 128x128 tile, BK=8, 256 threads, 8x8 per thread.
// ---------------------------------------------------------------------------
__global__ __launch_bounds__(256) void proj_kernel(
    const float* __restrict__ x,
    const float* __restrict__ Wq,
    const float* __restrict__ Wkv)
{
    __shared__ float As[8][128];
    __shared__ float Bs[8][128];

    const int tid = threadIdx.x;
    const int m0  = blockIdx.y * 128;
    const int n0  = blockIdx.x * 128;

    // whole 128-wide N tile lies inside Wq or Wkv (1024 % 128 == 0)
    const float* Wbase = (n0 < Dn) ? (Wq + (size_t)n0 * Dn)
                                   : (Wkv + (size_t)(n0 - Dn) * Dn);

    const int lr = tid >> 1;        // 0..127 row within tile
    const int lc = (tid & 1) * 4;   // 0 or 4 (k offset)

    const int rm = (tid & 15) * 8;  // 0..120
    const int rn = (tid >> 4) * 8;  // 0..120

    float c[8][8];
#pragma unroll
    for (int i = 0; i < 8; i++)
#pragma unroll
        for (int j = 0; j < 8; j++) c[i][j] = 0.f;

    for (int k0 = 0; k0 < Dn; k0 += 8) {
        float4 av = *(const float4*)(x     + (size_t)(m0 + lr) * Dn + k0 + lc);
        float4 bv = *(const float4*)(Wbase + (size_t)lr        * Dn + k0 + lc);
        As[lc + 0][lr] = av.x; As[lc + 1][lr] = av.y;
        As[lc + 2][lr] = av.z; As[lc + 3][lr] = av.w;
        Bs[lc + 0][lr] = bv.x; Bs[lc + 1][lr] = bv.y;
        Bs[lc + 2][lr] = bv.z; Bs[lc + 3][lr] = bv.w;
        __syncthreads();

#pragma unroll
        for (int kk = 0; kk < 8; kk++) {
            float4 a0 = *(float4*)&As[kk][rm];
            float4 a1 = *(float4*)&As[kk][rm + 4];
            float4 b0 = *(float4*)&Bs[kk][rn];
            float4 b1 = *(float4*)&Bs[kk][rn + 4];
            float a[8] = {a0.x, a0.y, a0.z, a0.w, a1.x, a1.y, a1.z, a1.w};
            float b[8] = {b0.x, b0.y, b0.z, b0.w, b1.x, b1.y, b1.z, b1.w};
#pragma unroll
            for (int i = 0; i < 8; i++)
#pragma unroll
                for (int j = 0; j < 8; j++) c[i][j] += a[i] * b[j];
        }
        __syncthreads();
    }

#pragma unroll
    for (int i = 0; i < 8; i++) {
        float* dst = g_y + (size_t)(m0 + rm + i) * NOUT + n0 + rn;
        *(float4*)(dst)     = make_float4(c[i][0], c[i][1], c[i][2], c[i][3]);
        *(float4*)(dst + 4) = make_float4(c[i][4], c[i][5], c[i][6], c[i][7]);
    }
}

// ---------------------------------------------------------------------------
// Kernel 2: S[b,h,i,j] = (1/32) * sum_d q[b,h,i,d] * k[b,h,j,d]
// 64 batched GEMMs of 1024x1024xK=64. 128x128 tile, BK=8.
// ---------------------------------------------------------------------------
__global__ __launch_bounds__(256) void score_kernel()
{
    __shared__ float As[8][128];
    __shared__ float Bs[8][128];

    const int tid = threadIdx.x;
    const int z   = blockIdx.z;           // b*16 + h
    const int b   = z >> 4;
    const int h   = z & 15;
    const int i0  = blockIdx.y * 128;
    const int j0  = blockIdx.x * 128;

    const float* qbase = g_y + (size_t)(b * Nn + i0) * NOUT + h * DHn;
    const float* kbase = g_y + (size_t)(b * Nn + j0) * NOUT + Dn + h * DHn;

    const int lr = tid >> 1;
    const int lc = (tid & 1) * 4;
    const int rm = (tid & 15) * 8;
    const int rn = (tid >> 4) * 8;

    float c[8][8];
#pragma unroll
    for (int i = 0; i < 8; i++)
#pragma unroll
        for (int j = 0; j < 8; j++) c[i][j] = 0.f;

    for (int k0 = 0; k0 < DHn; k0 += 8) {
        float4 av = *(const float4*)(qbase + (size_t)lr * NOUT + k0 + lc);
        float4 bv = *(const float4*)(kbase + (size_t)lr * NOUT + k0 + lc);
        As[lc + 0][lr] = av.x; As[lc + 1][lr] = av.y;
        As[lc + 2][lr] = av.z; As[lc + 3][lr] = av.w;
        Bs[lc + 0][lr] = bv.x; Bs[lc + 1][lr] = bv.y;
        Bs[lc + 2][lr] = bv.z; Bs[lc + 3][lr] = bv.w;
        __syncthreads();

#pragma unroll
        for (int kk = 0; kk < 8; kk++) {
            float4 a0 = *(float4*)&As[kk][rm];
            float4 a1 = *(float4*)&As[kk][rm + 4];
            float4 b0 = *(float4*)&Bs[kk][rn];
            float4 b1 = *(float4*)&Bs[kk][rn + 4];
            float a[8] = {a0.x, a0.y, a0.z, a0.w, a1.x, a1.y, a1.z, a1.w};
            float bb[8] = {b0.x, b0.y, b0.z, b0.w, b1.x, b1.y, b1.z, b1.w};
#pragma unroll
            for (int i = 0; i < 8; i++)
#pragma unroll
                for (int j = 0; j < 8; j++) c[i][j] += a[i] * bb[j];
        }
        __syncthreads();
    }

    const float scale = 0.03125f;  // 1024^-0.5
#pragma unroll
    for (int i = 0; i < 8; i++) {
        float* dst = g_s + ((size_t)z * Nn + (i0 + rm + i)) * Nn + j0 + rn;
        *(float4*)(dst)     = make_float4(c[i][0] * scale, c[i][1] * scale,
                                          c[i][2] * scale, c[i][3] * scale);
        *(float4*)(dst + 4) = make_float4(c[i][4] * scale, c[i][5] * scale,
                                          c[i][6] * scale, c[i][7] * scale);
    }
}

// ---------------------------------------------------------------------------
// Kernel 3: per (b,i) CTA — softmax(h,:), head-mix @ Wt^T, LN over h,
// argmax over j, fused hard-gather of v rows to d_out.
// ---------------------------------------------------------------------------
__global__ __launch_bounds__(512) void attn_kernel(
    const float* __restrict__ Wt,
    const float* __restrict__ ln_g,
    const float* __restrict__ ln_b,
    float* __restrict__ out)
{
    extern __shared__ float sm[];
    float* sw  = sm;                 // [16][1024]
    float* swt = sm + Hn * Nn;       // [256]
    float* sg  = swt + 256;          // [16]
    float* sb  = sg + 16;            // [16]

    const int tid = threadIdx.x;
    const int i   = blockIdx.x;
    const int b   = blockIdx.y;

    // load 16 score rows (64 KB)
    for (int f = tid; f < Hn * Nn / 4; f += 512) {
        int h  = f >> 8;
        int j4 = (f & 255) * 4;
        const float4 v = *(const float4*)(g_s + ((size_t)(b * Hn + h) * Nn + i) * Nn + j4);
        *(float4*)(sw + h * Nn + j4) = v;
    }
    if (tid < 256) swt[tid] = Wt[tid];
    if (tid < 16) { sg[tid] = ln_g[tid]; sb[tid] = ln_b[tid]; }
    __syncthreads();

    const int warp = tid >> 5;
    const int lane = tid & 31;

    // softmax per head (warp == head), jax-faithful: exp(x-max)/sum
    {
        float* row = sw + warp * Nn;
        float m = -INFINITY;
        for (int j = lane; j < Nn; j += 32) m = fmaxf(m, row[j]);
#pragma unroll
        for (int o = 16; o; o >>= 1) m = fmaxf(m, __shfl_xor_sync(~0u, m, o));
        float s = 0.f;
        for (int j = lane; j < Nn; j += 32) { float e = expf(row[j] - m); row[j] = e; s += e; }
#pragma unroll
        for (int o = 16; o; o >>= 1) s += __shfl_xor_sync(~0u, s, o);
        for (int j = lane; j < Nn; j += 32) row[j] = row[j] / s;
    }
    __syncthreads();

    // per-j: mix = Wt @ w_col, LayerNorm over heads; write back normalized
    for (int j = tid; j < Nn; j += 512) {
        float wc[16];
#pragma unroll
        for (int h = 0; h < 16; h++) wc[h] = sw[h * Nn + j];
        float mix[16];
        float mu = 0.f;
#pragma unroll
        for (int ho = 0; ho < 16; ho++) {
            float acc = 0.f;
#pragma unroll
            for (int h = 0; h < 16; h++) acc += swt[ho * 16 + h] * wc[h];
            mix[ho] = acc;
            mu += acc;
        }
        mu *= (1.f / 16.f);
        float var = 0.f;
#pragma unroll
        for (int ho = 0; ho < 16; ho++) { float d = mix[ho] - mu; var += d * d; }
        var *= (1.f / 16.f);
        const float denom = sqrtf(var + 1e-5f);
#pragma unroll
        for (int ho = 0; ho < 16; ho++)
            sw[ho * Nn + j] = (mix[ho] - mu) / denom * sg[ho] + sb[ho];
    }
    __syncthreads();

    // argmax over j per head (first-occurrence tie-break), then gather v row
    {
        const int h = warp;
        float* row = sw + h * Nn;
        float bv = -INFINITY;
        int   bi = 0;
        for (int j = lane; j < Nn; j += 32) {
            float v = row[j];
            if (v > bv) { bv = v; bi = j; }
        }
#pragma unroll
        for (int o = 16; o; o >>= 1) {
            float ov = __shfl_xor_sync(~0u, bv, o);
            int   oi = __shfl_xor_sync(~0u, bi, o);
            if (ov > bv || (ov == bv && oi < bi)) { bv = ov; bi = oi; }
        }
        // all lanes now agree on bi
        const float* vsrc = g_y + (size_t)(b * Nn + bi) * NOUT + 2 * Dn + h * DHn;
        float* dst = out + (size_t)(b * Nn + i) * Dn + h * DHn;
#pragma unroll
        for (int d = lane; d < DHn; d += 32) dst[d] = vsrc[d];
    }
}

// ---------------------------------------------------------------------------
extern "C" void kernel_launch(void* const* d_in, const int* in_sizes, int n_in,
                              void* d_out, int out_size)
{
    const float* x    = (const float*)d_in[0];
    const float* Wq   = (const float*)d_in[1];
    const float* Wkv  = (const float*)d_in[2];
    const float* Wt   = (const float*)d_in[3];
    const float* ln_g = (const float*)d_in[4];
    const float* ln_b = (const float*)d_in[5];
    float* out = (float*)d_out;

    proj_kernel<<<dim3(NOUT / 128, (Bn * Nn) / 128), 256>>>(x, Wq, Wkv);
    score_kernel<<<dim3(Nn / 128, Nn / 128, Bn * Hn), 256>>>();

    const int smem = (Hn * Nn + 256 + 16 + 16) * sizeof(float);
    cudaFuncSetAttribute(attn_kernel, cudaFuncAttributeMaxDynamicSharedMemorySize, smem);
    attn_kernel<<<dim3(Nn, Bn), 512, smem>>>(Wt, ln_g, ln_b, out);
}

// round 4
// speedup vs baseline: 1.1300x; 1.1300x over previous
#include <cuda_runtime.h>
#include <math.h>
#include <cstdint>

#define Bn   4
#define Nn   1024
#define Dn   1024
#define Hn   16
#define DHn  64
#define NOUT 3072   // q | k | v

__device__ float g_y[(size_t)Bn * Nn * NOUT];        // 50.3 MB  q|k|v
__device__ float g_s[(size_t)Bn * Hn * Nn * Nn];     // 268 MB   raw scores

// ---------------------------------------------------------------------------
// helpers
// ---------------------------------------------------------------------------
__device__ __forceinline__ uint32_t s2u(const void* p) {
    uint32_t a;
    asm("{ .reg .u64 t; cvta.to.shared.u64 t, %1; cvt.u32.u64 %0, t; }" : "=r"(a) : "l"(p));
    return a;
}
__device__ __forceinline__ void cp16(uint32_t s, const void* g) {
    asm volatile("cp.async.ca.shared.global [%0], [%1], 16;" :: "r"(s), "l"(g));
}
#define CP_COMMIT() asm volatile("cp.async.commit_group;" ::: "memory")
#define CP_WAIT(n)  asm volatile("cp.async.wait_group %0;" :: "n"(n) : "memory")

// 3-way bf16 split: f = b0 + b1 + b2 (+ O(2^-27))
__device__ __forceinline__ void split3(float f, unsigned short& u0,
                                       unsigned short& u1, unsigned short& u2) {
    unsigned short h0;
    asm("cvt.rn.bf16.f32 %0, %1;" : "=h"(h0) : "f"(f));
    float f0; asm("cvt.f32.bf16 %0, %1;" : "=f"(f0) : "h"(h0));
    float r1 = f - f0;
    unsigned short h1;
    asm("cvt.rn.bf16.f32 %0, %1;" : "=h"(h1) : "f"(r1));
    float f1; asm("cvt.f32.bf16 %0, %1;" : "=f"(f1) : "h"(h1));
    float r2 = r1 - f1;
    unsigned short h2;
    asm("cvt.rn.bf16.f32 %0, %1;" : "=h"(h2) : "f"(r2));
    u0 = h0; u1 = h1; u2 = h2;
}
// split a float2 (two consecutive-k values) into 3 packed bf16x2 regs
__device__ __forceinline__ void splitpack(float2 v, uint32_t& r0, uint32_t& r1, uint32_t& r2) {
    unsigned short a0, a1, a2, b0, b1, b2;
    split3(v.x, a0, a1, a2);
    split3(v.y, b0, b1, b2);
    r0 = (uint32_t)a0 | ((uint32_t)b0 << 16);
    r1 = (uint32_t)a1 | ((uint32_t)b1 << 16);
    r2 = (uint32_t)a2 | ((uint32_t)b2 << 16);
}
__device__ __forceinline__ void mma16(float* c, const uint32_t* a, uint32_t b0, uint32_t b1) {
    asm volatile(
        "mma.sync.aligned.m16n8k16.row.col.f32.bf16.bf16.f32 "
        "{%0,%1,%2,%3}, {%4,%5,%6,%7}, {%8,%9}, {%0,%1,%2,%3};"
        : "+f"(c[0]), "+f"(c[1]), "+f"(c[2]), "+f"(c[3])
        : "r"(a[0]), "r"(a[1]), "r"(a[2]), "r"(a[3]), "r"(b0), "r"(b1));
}

// ---------------------------------------------------------------------------
// shared GEMM body: 128x128 tile, BK=16, 256 thr (8 warps: 4 M x 2 N),
// bf16 split-3, 6 cross terms (error ~2^-27, below fp32 eps).
// C[m][n] = sum_k A[m][k] * B[n][k]
// ---------------------------------------------------------------------------
struct Frag { float acc[2][8][4]; };

__device__ __forceinline__ void gemm_tile(
    const float* __restrict__ aptr, size_t lda,
    const float* __restrict__ bptr, size_t ldb,
    int NK, float (*sA)[128][20], float (*sB)[128][20],
    Frag& F)
{
    const int tid  = threadIdx.x;
    const int lane = tid & 31;
    const int wid  = tid >> 5;
    const int wm   = wid & 3;     // 4 warps along M (32 rows each)
    const int wn   = wid >> 2;    // 2 warps along N (64 cols each)

#pragma unroll
    for (int mt = 0; mt < 2; mt++)
#pragma unroll
        for (int nt = 0; nt < 8; nt++)
#pragma unroll
            for (int r = 0; r < 4; r++) F.acc[mt][nt][r] = 0.f;

    // stage 0 load
    for (int c = tid; c < 512; c += 256) {
        int row = c >> 2, cp = c & 3;
        cp16(s2u(&sA[0][row][cp * 4]), aptr + (size_t)row * lda + cp * 4);
        cp16(s2u(&sB[0][row][cp * 4]), bptr + (size_t)row * ldb + cp * 4);
    }
    CP_COMMIT();

    for (int kt = 0; kt < NK; kt++) {
        if (kt + 1 < NK) {
            int st = (kt + 1) & 1;
            int k0 = (kt + 1) * 16;
            for (int c = tid; c < 512; c += 256) {
                int row = c >> 2, cp = c & 3;
                cp16(s2u(&sA[st][row][cp * 4]), aptr + (size_t)row * lda + k0 + cp * 4);
                cp16(s2u(&sB[st][row][cp * 4]), bptr + (size_t)row * ldb + k0 + cp * 4);
            }
            CP_COMMIT();
            CP_WAIT(1);
        } else {
            CP_WAIT(0);
        }
        __syncthreads();

        const int buf = kt & 1;
        const int k0  = (lane & 3) * 2;

        // A fragments: 3 levels x 4 regs per mt
        uint32_t Af[2][3][4];
#pragma unroll
        for (int mt = 0; mt < 2; mt++) {
            const int r0 = wm * 32 + mt * 16 + (lane >> 2);
            float2 p0 = *(const float2*)&sA[buf][r0][k0];
            float2 p1 = *(const float2*)&sA[buf][r0 + 8][k0];
            float2 p2 = *(const float2*)&sA[buf][r0][k0 + 8];
            float2 p3 = *(const float2*)&sA[buf][r0 + 8][k0 + 8];
            splitpack(p0, Af[mt][0][0], Af[mt][1][0], Af[mt][2][0]);
            splitpack(p1, Af[mt][0][1], Af[mt][1][1], Af[mt][2][1]);
            splitpack(p2, Af[mt][0][2], Af[mt][1][2], Af[mt][2][2]);
            splitpack(p3, Af[mt][0][3], Af[mt][1][3], Af[mt][2][3]);
        }

#pragma unroll
        for (int nt = 0; nt < 8; nt++) {
            const int n0 = wn * 64 + nt * 8 + (lane >> 2);
            float2 q0 = *(const float2*)&sB[buf][n0][k0];
            float2 q1 = *(const float2*)&sB[buf][n0][k0 + 8];
            uint32_t B0[3], B1[3];
            splitpack(q0, B0[0], B0[1], B0[2]);
            splitpack(q1, B1[0], B1[1], B1[2]);
#pragma unroll
            for (int mt = 0; mt < 2; mt++) {
                float* c = F.acc[mt][nt];
                mma16(c, Af[mt][0], B0[0], B1[0]);  // a0*b0
                mma16(c, Af[mt][0], B0[1], B1[1]);  // a0*b1
                mma16(c, Af[mt][1], B0[0], B1[0]);  // a1*b0
                mma16(c, Af[mt][1], B0[1], B1[1]);  // a1*b1
                mma16(c, Af[mt][0], B0[2], B1[2]);  // a0*b2
                mma16(c, Af[mt][2], B0[0], B1[0]);  // a2*b0
            }
        }
        __syncthreads();
    }
}

// ---------------------------------------------------------------------------
// Kernel 1: proj  Y[4096,3072] = x @ [Wq;Wkv]^T
// ---------------------------------------------------------------------------
__global__ __launch_bounds__(256) void proj_tc(
    const float* __restrict__ x,
    const float* __restrict__ Wq,
    const float* __restrict__ Wkv)
{
    __shared__ float sA[2][128][20];
    __shared__ float sB[2][128][20];

    const int m0 = blockIdx.y * 128;
    const int n0 = blockIdx.x * 128;
    const float* Wbase = (n0 < Dn) ? (Wq + (size_t)n0 * Dn)
                                   : (Wkv + (size_t)(n0 - Dn) * Dn);

    Frag F;
    gemm_tile(x + (size_t)m0 * Dn, Dn, Wbase, Dn, Dn / 16, sA, sB, F);

    const int lane = threadIdx.x & 31;
    const int wid  = threadIdx.x >> 5;
    const int wm = wid & 3, wn = wid >> 2;
#pragma unroll
    for (int mt = 0; mt < 2; mt++)
#pragma unroll
        for (int nt = 0; nt < 8; nt++) {
            int r  = m0 + wm * 32 + mt * 16 + (lane >> 2);
            int cc = n0 + wn * 64 + nt * 8 + (lane & 3) * 2;
            *(float2*)(g_y + (size_t)r * NOUT + cc) =
                make_float2(F.acc[mt][nt][0], F.acc[mt][nt][1]);
            *(float2*)(g_y + (size_t)(r + 8) * NOUT + cc) =
                make_float2(F.acc[mt][nt][2], F.acc[mt][nt][3]);
        }
}

// ---------------------------------------------------------------------------
// Kernel 2: score  S[b,h] = (q_h k_h^T) / 32   (64 batches, K=64)
// ---------------------------------------------------------------------------
__global__ __launch_bounds__(256) void score_tc()
{
    __shared__ float sA[2][128][20];
    __shared__ float sB[2][128][20];

    const int jt = blockIdx.x, it = blockIdx.y, z = blockIdx.z;
    const int b = z >> 4, h = z & 15;

    const float* qbase = g_y + (size_t)(b * Nn + it * 128) * NOUT + h * DHn;
    const float* kbase = g_y + (size_t)(b * Nn + jt * 128) * NOUT + Dn + h * DHn;

    Frag F;
    gemm_tile(qbase, NOUT, kbase, NOUT, DHn / 16, sA, sB, F);

    const int lane = threadIdx.x & 31;
    const int wid  = threadIdx.x >> 5;
    const int wm = wid & 3, wn = wid >> 2;
    const float scale = 0.03125f;
#pragma unroll
    for (int mt = 0; mt < 2; mt++)
#pragma unroll
        for (int nt = 0; nt < 8; nt++) {
            int r  = it * 128 + wm * 32 + mt * 16 + (lane >> 2);
            int cc = jt * 128 + wn * 64 + nt * 8 + (lane & 3) * 2;
            float* base = g_s + ((size_t)z * Nn + r) * Nn + cc;
            *(float2*)base =
                make_float2(F.acc[mt][nt][0] * scale, F.acc[mt][nt][1] * scale);
            *(float2*)(base + 8 * Nn) =
                make_float2(F.acc[mt][nt][2] * scale, F.acc[mt][nt][3] * scale);
        }
}

// ---------------------------------------------------------------------------
// Kernel 3: attn — per (b,i): softmax(h,:), head-mix @ Wt^T, LN over h,
// argmax over j, hard v-row gather to d_out.
// ---------------------------------------------------------------------------
__global__ __launch_bounds__(512) void attn_kernel(
    const float* __restrict__ Wt,
    const float* __restrict__ ln_g,
    const float* __restrict__ ln_b,
    float* __restrict__ out)
{
    extern __shared__ float sm[];
    float* sw  = sm;
    float* swt = sm + Hn * Nn;
    float* sg  = swt + 256;
    float* sb  = sg + 16;

    const int tid = threadIdx.x;
    const int i   = blockIdx.x;
    const int b   = blockIdx.y;

    for (int f = tid; f < Hn * Nn / 4; f += 512) {
        int h = f >> 8;
        int j4 = (f & 255) * 4;
        const float4 v = *(const float4*)(g_s + ((size_t)(b * Hn + h) * Nn + i) * Nn + j4);
        *(float4*)(sw + h * Nn + j4) = v;
    }
    if (tid < 256) swt[tid] = Wt[tid];
    if (tid < 16) { sg[tid] = ln_g[tid]; sb[tid] = ln_b[tid]; }
    __syncthreads();

    const int warp = tid >> 5;
    const int lane = tid & 31;

    {
        float* row = sw + warp * Nn;
        float m = -INFINITY;
        for (int j = lane; j < Nn; j += 32) m = fmaxf(m, row[j]);
#pragma unroll
        for (int o = 16; o; o >>= 1) m = fmaxf(m, __shfl_xor_sync(~0u, m, o));
        float s = 0.f;
        for (int j = lane; j < Nn; j += 32) { float e = expf(row[j] - m); row[j] = e; s += e; }
#pragma unroll
        for (int o = 16; o; o >>= 1) s += __shfl_xor_sync(~0u, s, o);
        for (int j = lane; j < Nn; j += 32) row[j] = row[j] / s;
    }
    __syncthreads();

    for (int j = tid; j < Nn; j += 512) {
        float wc[16];
#pragma unroll
        for (int h = 0; h < 16; h++) wc[h] = sw[h * Nn + j];
        float mix[16];
        float mu = 0.f;
#pragma unroll
        for (int ho = 0; ho < 16; ho++) {
            float acc = 0.f;
#pragma unroll
            for (int h = 0; h < 16; h++) acc += swt[ho * 16 + h] * wc[h];
            mix[ho] = acc;
            mu += acc;
        }
        mu *= (1.f / 16.f);
        float var = 0.f;
#pragma unroll
        for (int ho = 0; ho < 16; ho++) { float d = mix[ho] - mu; var += d * d; }
        var *= (1.f / 16.f);
        const float denom = sqrtf(var + 1e-5f);
#pragma unroll
        for (int ho = 0; ho < 16; ho++)
            sw[ho * Nn + j] = (mix[ho] - mu) / denom * sg[ho] + sb[ho];
    }
    __syncthreads();

    {
        const int h = warp;
        float* row = sw + h * Nn;
        float bv = -INFINITY;
        int   bi = 0;
        for (int j = lane; j < Nn; j += 32) {
            float v = row[j];
            if (v > bv) { bv = v; bi = j; }
        }
#pragma unroll
        for (int o = 16; o; o >>= 1) {
            float ov = __shfl_xor_sync(~0u, bv, o);
            int   oi = __shfl_xor_sync(~0u, bi, o);
            if (ov > bv || (ov == bv && oi < bi)) { bv = ov; bi = oi; }
        }
        const float* vsrc = g_y + (size_t)(b * Nn + bi) * NOUT + 2 * Dn + h * DHn;
        float* dst = out + (size_t)(b * Nn + i) * Dn + h * DHn;
#pragma unroll
        for (int d = lane; d < DHn; d += 32) dst[d] = vsrc[d];
    }
}

// ---------------------------------------------------------------------------
extern "C" void kernel_launch(void* const* d_in, const int* in_sizes, int n_in,
                              void* d_out, int out_size)
{
    const float* x    = (const float*)d_in[0];
    const float* Wq   = (const float*)d_in[1];
    const float* Wkv  = (const float*)d_in[2];
    const float* Wt   = (const float*)d_in[3];
    const float* ln_g = (const float*)d_in[4];
    const float* ln_b = (const float*)d_in[5];
    float* out = (float*)d_out;

    proj_tc<<<dim3(NOUT / 128, (Bn * Nn) / 128), 256>>>(x, Wq, Wkv);
    score_tc<<<dim3(Nn / 128, Nn / 128, Bn * Hn), 256>>>();

    const int asmem = (Hn * Nn + 256 + 16 + 16) * sizeof(float);
    cudaFuncSetAttribute(attn_kernel, cudaFuncAttributeMaxDynamicSharedMemorySize, asmem);
    attn_kernel<<<dim3(Nn, Bn), 512, asmem>>>(Wt, ln_g, ln_b, out);
}